// round 11
// baseline (speedup 1.0000x reference)
#include <cuda_runtime.h>
#include <cuda_fp16.h>
#include <cstdint>

// Problem constants
#define B_SZ 256
#define W_SZ 4096
#define L_SZ 16
#define K_SZ 8

#define NLEVELS (L_SZ - 1)    // 15
#define NCTA 512              // 512 CTAs x 256 thr = 4096 warps = W (one warp per n)

// One buffer per level boundary: g_buf[l] = activations entering level l.
// 16 * 4096 * 256 * 2B = 32 MB. Every address written ONCE per launch.
__device__ __half g_buf[L_SZ][(size_t)W_SZ * B_SZ];

// Dataflow flags: g_flag[l][n] == 1  <=>  g_buf[l+1] row n is ready. l = 0..13.
__device__ unsigned g_flag[(NLEVELS - 1) * W_SZ];

// Detected element width of inv_mask input: 1 (bool/uint8) or 4 (int32/float32).
__device__ int g_inv_width;

// L2-scope scalar flag ops (must bypass L1 and defeat compiler CSE).
__device__ __forceinline__ unsigned ldcg_u32(const unsigned* p) {
    unsigned v;
    asm volatile("ld.global.cg.u32 %0, [%1];" : "=r"(v) : "l"(p));
    return v;
}
__device__ __forceinline__ void stcg_u32(unsigned* p, unsigned v) {
    asm volatile("st.global.cg.u32 [%0], %1;" :: "l"(p), "r"(v) : "memory");
}

// ---------------------------------------------------------------------------
// Kernel 1: fused prior + transpose + inv width detect + flag reset.
//   g_buf[0][n][b] = (half) relu(obs[b][n] * pw[n] + pb[n])
// ---------------------------------------------------------------------------
__global__ void __launch_bounds__(256) prior_transpose_kernel(
    const float* __restrict__ obs,
    const float* __restrict__ pw,
    const float* __restrict__ pb,
    const unsigned char* __restrict__ inv)
{
    const int tid = threadIdx.y * 32 + threadIdx.x;                 // 0..255
    const int bid = blockIdx.y * gridDim.x + blockIdx.x;

    // Grid-stride flag reset (57344 words over 262144 threads).
    {
        int g = bid * 256 + tid;
        if (g < (NLEVELS - 1) * W_SZ) g_flag[g] = 0u;
    }

    // inv width detection: for 4-byte encodings of {0,1}, byte at offset
    // ==1 (mod 4) is always 0; for 1-byte bools it's ~Bernoulli(0.5).
    if (blockIdx.x == 0 && blockIdx.y == 0) {
        const int pred = (inv[tid * 4 + 1] != 0) ? 1 : 0;
        const int any = __syncthreads_or(pred);
        if (tid == 0) g_inv_width = any ? 1 : 4;
    }

    __shared__ float tile[32][33];
    const int n0 = blockIdx.x * 32;
    const int b0 = blockIdx.y * 32;
    const int tx = threadIdx.x;   // 0..31
    const int ty = threadIdx.y;   // 0..7

#pragma unroll
    for (int j = 0; j < 4; j++) {
        int b = b0 + ty + j * 8;
        tile[ty + j * 8][tx] = obs[(size_t)b * W_SZ + n0 + tx];  // tile[b_local][n_local]
    }
    __syncthreads();
#pragma unroll
    for (int j = 0; j < 4; j++) {
        int n = n0 + ty + j * 8;
        int b = b0 + tx;
        float v = tile[tx][ty + j * 8];
        v = fmaxf(fmaf(v, __ldg(pw + n), __ldg(pb + n)), 0.0f);
        g_buf[0][(size_t)n * B_SZ + b] = __float2half_rn(v);
    }
#if __CUDA_ARCH__ >= 900
    cudaTriggerProgrammaticLaunchCompletion();
#endif
}

// ---------------------------------------------------------------------------
// Kernel 2: persistent dataflow scan — all 15 levels, no barriers.
// Warp w owns row n=w at every level. Before level l>0 it polls only its 8
// parents' flags; after storing its row it fences and sets its own flag.
// All 512 CTAs are co-resident (launch_bounds(256,4): 4*148=592 >= 512), so
// producers always make progress -> no deadlock.
// ---------------------------------------------------------------------------
__global__ void __launch_bounds__(256, 4) scan_kernel(
    const float*         __restrict__ weights,   // [L-1][W][K]
    const float*         __restrict__ biases,    // [L-1][W]
    const int*           __restrict__ parents,   // [L-1][W][K]
    const unsigned char* __restrict__ inv_base)  // [L-1][W]
{
    const int lane = threadIdx.x & 31;
    const int n    = (blockIdx.x * 256 + threadIdx.x) >> 5;  // global warp id
    const int b    = lane << 3;                              // 8-half batch slice

    // ---- PDL prologue: level-0 parents/bias (pure inputs) ----
    int4 p0, p1; float bb;
    {
        const int4* pp = reinterpret_cast<const int4*>(parents + (size_t)n * K_SZ);
        p0 = __ldg(pp); p1 = __ldg(pp + 1);
        bb = __ldg(biases + n);
    }

#if __CUDA_ARCH__ >= 900
    cudaGridDependencySynchronize();   // prior kernel done: g_buf[0], flags, width
#endif
    const int invw = g_inv_width;

#pragma unroll 1
    for (int l = 0; l < NLEVELS; l++) {
        // ---- wait for the 8 parent rows (levels > 0 only) ----
        if (l > 0) {
            const unsigned* fl = g_flag + (size_t)(l - 1) * W_SZ;
            int c = lane & 3;
            int4 ps = (lane & 4) ? p1 : p0;
            int fi = (c == 0) ? ps.x : (c == 1) ? ps.y : (c == 2) ? ps.z : ps.w;
            long long spins = 0;
            for (;;) {
                unsigned v = (lane < 8) ? ldcg_u32(fl + fi) : 1u;
                if (__ballot_sync(0xffffffffu, v != 0u) == 0xffffffffu) break;
                if (++spins > (1LL << 26)) break;   // termination valve
                __nanosleep(64);
            }
            __threadfence();                        // acquire
        }

        // ---- issue all 8 gathers (L2-scope; MLP = 8) ----
        const __half* hb = g_buf[l] + b;
        const int4* a0 = reinterpret_cast<const int4*>(hb + (((size_t)p0.x) << 8));
        const int4* a1 = reinterpret_cast<const int4*>(hb + (((size_t)p0.y) << 8));
        const int4* a2 = reinterpret_cast<const int4*>(hb + (((size_t)p0.z) << 8));
        const int4* a3 = reinterpret_cast<const int4*>(hb + (((size_t)p0.w) << 8));
        const int4* a4 = reinterpret_cast<const int4*>(hb + (((size_t)p1.x) << 8));
        const int4* a5 = reinterpret_cast<const int4*>(hb + (((size_t)p1.y) << 8));
        const int4* a6 = reinterpret_cast<const int4*>(hb + (((size_t)p1.z) << 8));
        const int4* a7 = reinterpret_cast<const int4*>(hb + (((size_t)p1.w) << 8));
        int4 r0 = __ldcg(a0);
        int4 r1 = __ldcg(a1);
        int4 r2 = __ldcg(a2);
        int4 r3 = __ldcg(a3);
        int4 r4 = __ldcg(a4);
        int4 r5 = __ldcg(a5);
        int4 r6 = __ldcg(a6);
        int4 r7 = __ldcg(a7);

        // ---- loads that overlap the gather wait: weights+inv (this level),
        //      parents+bias (next level) ----
        const float4* wp = reinterpret_cast<const float4*>(weights + (size_t)l * W_SZ * K_SZ + (size_t)n * K_SZ);
        float4 w0 = __ldg(wp);
        float4 w1 = __ldg(wp + 1);
        bool iv;
        if (invw == 4) {
            const unsigned* iw = reinterpret_cast<const unsigned*>(inv_base);
            iv = (__ldg(iw + (size_t)l * W_SZ + n) != 0u);
        } else {
            iv = (__ldg(inv_base + (size_t)l * W_SZ + n) != 0);
        }
        int4 np0 = p0, np1 = p1; float nbb = bb;
        if (l < NLEVELS - 1) {
            const int4* pp = reinterpret_cast<const int4*>(parents + (size_t)(l + 1) * W_SZ * K_SZ + (size_t)n * K_SZ);
            np0 = __ldg(pp); np1 = __ldg(pp + 1);
            nbb = __ldg(biases + (size_t)(l + 1) * W_SZ + n);
        }

        // Fold inversion:  Σ w*(1-x) + b == (b + Σw) - Σ w*x
        float sw = ((w0.x + w0.y) + (w0.z + w0.w)) + ((w1.x + w1.y) + (w1.z + w1.w));
        float basev = iv ? (bb + sw) : bb;
        float sgn   = iv ? -1.0f : 1.0f;

        float acc[8];
#pragma unroll
        for (int i = 0; i < 8; i++) acc[i] = 0.0f;

#define ACCUM(RAW, WV)                                                         \
    {                                                                          \
        float2 f0 = __half22float2(*reinterpret_cast<__half2*>(&(RAW).x));     \
        float2 f1 = __half22float2(*reinterpret_cast<__half2*>(&(RAW).y));     \
        float2 f2 = __half22float2(*reinterpret_cast<__half2*>(&(RAW).z));     \
        float2 f3 = __half22float2(*reinterpret_cast<__half2*>(&(RAW).w));     \
        acc[0] = fmaf((WV), f0.x, acc[0]); acc[1] = fmaf((WV), f0.y, acc[1]);  \
        acc[2] = fmaf((WV), f1.x, acc[2]); acc[3] = fmaf((WV), f1.y, acc[3]);  \
        acc[4] = fmaf((WV), f2.x, acc[4]); acc[5] = fmaf((WV), f2.y, acc[5]);  \
        acc[6] = fmaf((WV), f3.x, acc[6]); acc[7] = fmaf((WV), f3.y, acc[7]);  \
    }
        ACCUM(r0, w0.x)
        ACCUM(r1, w0.y)
        ACCUM(r2, w0.z)
        ACCUM(r3, w0.w)
        ACCUM(r4, w1.x)
        ACCUM(r5, w1.y)
        ACCUM(r6, w1.z)
        ACCUM(r7, w1.w)
#undef ACCUM

#pragma unroll
        for (int i = 0; i < 8; i++) acc[i] = fmaxf(fmaf(sgn, acc[i], basev), 0.0f);

        __half2 o0 = __floats2half2_rn(acc[0], acc[1]);
        __half2 o1 = __floats2half2_rn(acc[2], acc[3]);
        __half2 o2 = __floats2half2_rn(acc[4], acc[5]);
        __half2 o3 = __floats2half2_rn(acc[6], acc[7]);
        int4 outv;
        outv.x = *reinterpret_cast<int*>(&o0);
        outv.y = *reinterpret_cast<int*>(&o1);
        outv.z = *reinterpret_cast<int*>(&o2);
        outv.w = *reinterpret_cast<int*>(&o3);
        *reinterpret_cast<int4*>(g_buf[l + 1] + (size_t)n * B_SZ + b) = outv;

        // ---- release: publish the row, then set the flag ----
        if (l < NLEVELS - 1) {
            __threadfence();
            __syncwarp();
            if (lane == 0) stcg_u32(g_flag + (size_t)l * W_SZ + n, 1u);
        }

        p0 = np0; p1 = np1; bb = nbb;
    }

#if __CUDA_ARCH__ >= 900
    cudaTriggerProgrammaticLaunchCompletion();
#endif
}

// ---------------------------------------------------------------------------
// Kernel 3: final transpose back to reference layout (half -> float).
//   out[b][n] = (float) g_buf[15][n][b]
// ---------------------------------------------------------------------------
__global__ void __launch_bounds__(256) out_transpose_kernel(float* __restrict__ out)
{
#if __CUDA_ARCH__ >= 900
    cudaGridDependencySynchronize();
#endif
    __shared__ float tile[32][33];
    const int b0 = blockIdx.x * 32;
    const int n0 = blockIdx.y * 32;
    const int tx = threadIdx.x;
    const int ty = threadIdx.y;

#pragma unroll
    for (int j = 0; j < 4; j++) {
        int n = n0 + ty + j * 8;
        tile[ty + j * 8][tx] = __half2float(g_buf[NLEVELS][(size_t)n * B_SZ + b0 + tx]);
    }
    __syncthreads();
#pragma unroll
    for (int j = 0; j < 4; j++) {
        int b = b0 + ty + j * 8;
        out[(size_t)b * W_SZ + n0 + tx] = tile[tx][ty + j * 8];
    }
}

// ---------------------------------------------------------------------------
// Launch: prior -> scan -> transpose, PDL-chained.
// ---------------------------------------------------------------------------
extern "C" void kernel_launch(void* const* d_in, const int* in_sizes, int n_in,
                              void* d_out, int out_size)
{
    const float*         obs     = (const float*)d_in[0];         // [B, W]
    const float*         pw      = (const float*)d_in[1];         // [W]
    const float*         pb      = (const float*)d_in[2];         // [W]
    const float*         weights = (const float*)d_in[3];         // [L-1, W, K]
    const float*         biases  = (const float*)d_in[4];         // [L-1, W]
    const int*           parents = (const int*)d_in[5];           // [L-1, W, K]
    const unsigned char* inv     = (const unsigned char*)d_in[6]; // [L-1, W]
    float*               out     = (float*)d_out;                 // [B, W]

    (void)in_sizes; (void)n_in; (void)out_size;

    // Prior + transpose into g_buf[0]; resets flags; detects inv width.
    prior_transpose_kernel<<<dim3(W_SZ / 32, B_SZ / 32), dim3(32, 8)>>>(obs, pw, pb, inv);

    cudaLaunchAttribute attrs[1];
    attrs[0].id = cudaLaunchAttributeProgrammaticStreamSerialization;
    attrs[0].val.programmaticStreamSerializationAllowed = 1;

    // Whole scan in one persistent dataflow launch.
    {
        cudaLaunchConfig_t cfg = {};
        cfg.gridDim  = dim3(NCTA, 1, 1);
        cfg.blockDim = dim3(256, 1, 1);
        cfg.dynamicSmemBytes = 0;
        cfg.stream = 0;
        cfg.attrs = attrs;
        cfg.numAttrs = 1;
        cudaLaunchKernelEx(&cfg, scan_kernel, weights, biases, parents, inv);
    }

    // Transpose final activations (g_buf[15]) to output layout.
    {
        cudaLaunchConfig_t cfg = {};
        cfg.gridDim  = dim3(B_SZ / 32, W_SZ / 32, 1);
        cfg.blockDim = dim3(32, 8, 1);
        cfg.dynamicSmemBytes = 0;
        cfg.stream = 0;
        cfg.attrs = attrs;
        cfg.numAttrs = 1;
        cudaLaunchKernelEx(&cfg, out_transpose_kernel, out);
    }
}

// round 12
// speedup vs baseline: 3.4871x; 3.4871x over previous
#include <cuda_runtime.h>
#include <cuda_fp16.h>
#include <cstdint>

// Problem constants
#define B_SZ 256
#define W_SZ 4096
#define L_SZ 16
#define K_SZ 8

// Ping-pong activation scratch, fp16, transposed layout: h_t[n][b] (b fast).
// 2 * 4096 * 256 * 2B = 4 MB  -> fully L2-resident.
__device__ __half g_h[2][(size_t)W_SZ * B_SZ];

// Detected element width of inv_mask input: 1 (bool/uint8) or 4 (int32/float32).
__device__ int g_inv_width;

// ---------------------------------------------------------------------------
// Kernel 1: fused prior + transpose (+ PARALLEL inv width detection, block 0).
//   h_t[n][b] = (half) relu(obs[b][n] * pw[n] + pb[n])
// ---------------------------------------------------------------------------
__global__ void __launch_bounds__(256) prior_transpose_kernel(
    const float* __restrict__ obs,
    const float* __restrict__ pw,
    const float* __restrict__ pb,
    const unsigned char* __restrict__ inv)
{
    if (blockIdx.x == 0 && blockIdx.y == 0) {
        const int t = threadIdx.y * 32 + threadIdx.x;          // 0..255
        const int pred = (inv[t * 4 + 1] != 0) ? 1 : 0;        // coalesced
        const int any = __syncthreads_or(pred);
        if (t == 0) g_inv_width = any ? 1 : 4;
    }

    __shared__ float tile[32][33];
    const int n0 = blockIdx.x * 32;
    const int b0 = blockIdx.y * 32;
    const int tx = threadIdx.x;   // 0..31
    const int ty = threadIdx.y;   // 0..7

#pragma unroll
    for (int j = 0; j < 4; j++) {
        int b = b0 + ty + j * 8;
        tile[ty + j * 8][tx] = obs[(size_t)b * W_SZ + n0 + tx];  // tile[b_local][n_local]
    }
    __syncthreads();
#pragma unroll
    for (int j = 0; j < 4; j++) {
        int n = n0 + ty + j * 8;
        int b = b0 + tx;
        float v = tile[tx][ty + j * 8];
        v = fmaxf(fmaf(v, __ldg(pw + n), __ldg(pb + n)), 0.0f);
        g_h[0][(size_t)n * B_SZ + b] = __float2half_rn(v);
    }
#if __CUDA_ARCH__ >= 900
    cudaTriggerProgrammaticLaunchCompletion();
#endif
}

// ---------------------------------------------------------------------------
// Shared level math: PDL prologue loads params + gather addresses; post-sync
// all 8 LDG.128 gathers issue back-to-back (MLP=8), then convert+FMA.
// Returns the 8 fp32 relu outputs for (n, b..b+7) in acc[].
// ---------------------------------------------------------------------------
__device__ __forceinline__ void level_math(
    int src, int lvl, int n, int b,
    const float*         __restrict__ weights,
    const float*         __restrict__ biases,
    const int*           __restrict__ parents,
    const unsigned char* __restrict__ inv_base,
    float acc[8])
{
    // ---- PDL prologue: input-only loads + address math ----
    const int4*   pp = reinterpret_cast<const int4*>(parents + (size_t)n * K_SZ);
    const float4* wp = reinterpret_cast<const float4*>(weights + (size_t)n * K_SZ);
    int4   p0 = __ldg(pp);
    int4   p1 = __ldg(pp + 1);
    float4 w0 = __ldg(wp);
    float4 w1 = __ldg(wp + 1);
    float  bb = __ldg(biases + n);
    float  sw = ((w0.x + w0.y) + (w0.z + w0.w)) + ((w1.x + w1.y) + (w1.z + w1.w));
    float  base_inv = bb + sw;

    const __half* hb = g_h[src] + b;
    const int4* a0 = reinterpret_cast<const int4*>(hb + (((size_t)p0.x) << 8));
    const int4* a1 = reinterpret_cast<const int4*>(hb + (((size_t)p0.y) << 8));
    const int4* a2 = reinterpret_cast<const int4*>(hb + (((size_t)p0.z) << 8));
    const int4* a3 = reinterpret_cast<const int4*>(hb + (((size_t)p0.w) << 8));
    const int4* a4 = reinterpret_cast<const int4*>(hb + (((size_t)p1.x) << 8));
    const int4* a5 = reinterpret_cast<const int4*>(hb + (((size_t)p1.y) << 8));
    const int4* a6 = reinterpret_cast<const int4*>(hb + (((size_t)p1.z) << 8));
    const int4* a7 = reinterpret_cast<const int4*>(hb + (((size_t)p1.w) << 8));

#if __CUDA_ARCH__ >= 900
    cudaGridDependencySynchronize();   // previous level's stores now visible
#endif

    // ---- all 8 gathers in flight before any consumption (MLP = 8) ----
    int4 r0 = __ldg(a0);
    int4 r1 = __ldg(a1);
    int4 r2 = __ldg(a2);
    int4 r3 = __ldg(a3);
    int4 r4 = __ldg(a4);
    int4 r5 = __ldg(a5);
    int4 r6 = __ldg(a6);
    int4 r7 = __ldg(a7);

#pragma unroll
    for (int i = 0; i < 8; i++) acc[i] = 0.0f;

#define ACCUM(RAW, WV)                                                         \
    {                                                                          \
        float2 f0 = __half22float2(*reinterpret_cast<__half2*>(&(RAW).x));     \
        float2 f1 = __half22float2(*reinterpret_cast<__half2*>(&(RAW).y));     \
        float2 f2 = __half22float2(*reinterpret_cast<__half2*>(&(RAW).z));     \
        float2 f3 = __half22float2(*reinterpret_cast<__half2*>(&(RAW).w));     \
        acc[0] = fmaf((WV), f0.x, acc[0]); acc[1] = fmaf((WV), f0.y, acc[1]);  \
        acc[2] = fmaf((WV), f1.x, acc[2]); acc[3] = fmaf((WV), f1.y, acc[3]);  \
        acc[4] = fmaf((WV), f2.x, acc[4]); acc[5] = fmaf((WV), f2.y, acc[5]);  \
        acc[6] = fmaf((WV), f3.x, acc[6]); acc[7] = fmaf((WV), f3.y, acc[7]);  \
    }
    ACCUM(r0, w0.x)
    ACCUM(r1, w0.y)
    ACCUM(r2, w0.z)
    ACCUM(r3, w0.w)
    ACCUM(r4, w1.x)
    ACCUM(r5, w1.y)
    ACCUM(r6, w1.z)
    ACCUM(r7, w1.w)
#undef ACCUM

    // inv resolution (post-sync; hides under the gathers above).
    bool iv;
    if (g_inv_width == 4) {
        const unsigned* iw = reinterpret_cast<const unsigned*>(inv_base);
        iv = (__ldg(iw + (size_t)lvl * W_SZ + n) != 0u);
    } else {
        iv = (__ldg(inv_base + (size_t)lvl * W_SZ + n) != 0);
    }
    //  Σ w*(1-x) + b == (b + Σw) - Σ w*x
    float basev = iv ? base_inv : bb;
    float sgn   = iv ? -1.0f : 1.0f;

#pragma unroll
    for (int i = 0; i < 8; i++) acc[i] = fmaxf(fmaf(sgn, acc[i], basev), 0.0f);
}

// ---------------------------------------------------------------------------
// Kernel 2a: intermediate scan level (0..13) — stores fp16 to ping-pong.
// ---------------------------------------------------------------------------
__global__ void __launch_bounds__(256, 4) level_kernel(
    int src,
    int lvl,
    const float*         __restrict__ weights,
    const float*         __restrict__ biases,
    const int*           __restrict__ parents,
    const unsigned char* __restrict__ inv_base)
{
    const int gid = blockIdx.x * 256 + threadIdx.x;
    const int n   = gid >> 5;          // 32 threads per n
    const int b   = (gid & 31) << 3;   // lane's 8-wide batch slice

    float acc[8];
    level_math(src, lvl, n, b, weights, biases, parents, inv_base, acc);

    __half2 o0 = __floats2half2_rn(acc[0], acc[1]);
    __half2 o1 = __floats2half2_rn(acc[2], acc[3]);
    __half2 o2 = __floats2half2_rn(acc[4], acc[5]);
    __half2 o3 = __floats2half2_rn(acc[6], acc[7]);
    int4 outv;
    outv.x = *reinterpret_cast<int*>(&o0);
    outv.y = *reinterpret_cast<int*>(&o1);
    outv.z = *reinterpret_cast<int*>(&o2);
    outv.w = *reinterpret_cast<int*>(&o3);
    *reinterpret_cast<int4*>(g_h[src ^ 1] + (size_t)n * B_SZ + b) = outv;

#if __CUDA_ARCH__ >= 900
    cudaTriggerProgrammaticLaunchCompletion();
#endif
}

// ---------------------------------------------------------------------------
// Kernel 2b: FINAL level (14) — fused output transpose.
// CTA covers 8 consecutive n. fp32 results staged in a bank-conflict-free
// smem tile (pitch 260: bank = (4n + b) % 32), then written to out[b][n]
// as fully-utilized 32B sectors. Skips the fp16 round-trip entirely.
// ---------------------------------------------------------------------------
#define TILE_PITCH 260
__global__ void __launch_bounds__(256, 4) level_out_kernel(
    int src,
    int lvl,
    const float*         __restrict__ weights,
    const float*         __restrict__ biases,
    const int*           __restrict__ parents,
    const unsigned char* __restrict__ inv_base,
    float* __restrict__ out)
{
    __shared__ float tile[8 * TILE_PITCH];

    const int lane = threadIdx.x & 31;
    const int w    = threadIdx.x >> 5;         // warp id in CTA = local n
    const int n0   = blockIdx.x * 8;
    const int n    = n0 + w;
    const int b    = lane << 3;

    float acc[8];
    level_math(src, lvl, n, b, weights, biases, parents, inv_base, acc);

    // Stage: tile[w][b..b+7] = acc (two float4 stores; 16B aligned since
    // w*260 and lane*8 are both multiples of 4 words).
    float* tp = tile + w * TILE_PITCH + b;
    *reinterpret_cast<float4*>(tp)     = make_float4(acc[0], acc[1], acc[2], acc[3]);
    *reinterpret_cast<float4*>(tp + 4) = make_float4(acc[4], acc[5], acc[6], acc[7]);
    __syncthreads();

    // Write: warp w owns b-range [w*32, w*32+32). Each iteration, 32 lanes
    // cover 4 b's x 8 n's -> 4 fully-utilized 32B sectors in out.
    const int nn = lane & 7;          // 0..7  (n offset)
    const int bq = lane >> 3;         // 0..3  (b offset within group)
#pragma unroll
    for (int j = 0; j < 8; j++) {
        int bb = w * 32 + j * 4 + bq;
        float v = tile[nn * TILE_PITCH + bb];   // banks (4*nn'... ) all distinct
        out[(size_t)bb * W_SZ + n0 + nn] = v;
    }
}

// ---------------------------------------------------------------------------
// Launch: prior -> 14 intermediate levels -> fused final level, PDL-chained.
// ---------------------------------------------------------------------------
extern "C" void kernel_launch(void* const* d_in, const int* in_sizes, int n_in,
                              void* d_out, int out_size)
{
    const float*         obs     = (const float*)d_in[0];         // [B, W]
    const float*         pw      = (const float*)d_in[1];         // [W]
    const float*         pb      = (const float*)d_in[2];         // [W]
    const float*         weights = (const float*)d_in[3];         // [L-1, W, K]
    const float*         biases  = (const float*)d_in[4];         // [L-1, W]
    const int*           parents = (const int*)d_in[5];           // [L-1, W, K]
    const unsigned char* inv     = (const unsigned char*)d_in[6]; // [L-1, W]
    float*               out     = (float*)d_out;                 // [B, W]

    (void)in_sizes; (void)n_in; (void)out_size;

    // Prior + transpose into g_h[0] (also detects inv_mask element width)
    prior_transpose_kernel<<<dim3(W_SZ / 32, B_SZ / 32), dim3(32, 8)>>>(obs, pw, pb, inv);

    cudaLaunchAttribute attrs[1];
    attrs[0].id = cudaLaunchAttributeProgrammaticStreamSerialization;
    attrs[0].val.programmaticStreamSerializationAllowed = 1;

    const int blocks = (W_SZ * 32) / 256;  // 512

    // Levels 0..13: ping-pong g_h[0] <-> g_h[1], PDL-chained.
    for (int l = 0; l < L_SZ - 2; l++) {
        cudaLaunchConfig_t cfg = {};
        cfg.gridDim  = dim3(blocks, 1, 1);
        cfg.blockDim = dim3(256, 1, 1);
        cfg.dynamicSmemBytes = 0;
        cfg.stream = 0;
        cfg.attrs = attrs;
        cfg.numAttrs = 1;
        cudaLaunchKernelEx(&cfg, level_kernel,
            l & 1, l,
            (const float*)(weights + (size_t)l * W_SZ * K_SZ),
            (const float*)(biases  + (size_t)l * W_SZ),
            (const int*)(parents + (size_t)l * W_SZ * K_SZ),
            (const unsigned char*)inv);
    }

    // Level 14: fused final level + output transpose (fp32, direct to out).
    {
        const int l = L_SZ - 2;  // 14
        cudaLaunchConfig_t cfg = {};
        cfg.gridDim  = dim3(blocks, 1, 1);
        cfg.blockDim = dim3(256, 1, 1);
        cfg.dynamicSmemBytes = 0;
        cfg.stream = 0;
        cfg.attrs = attrs;
        cfg.numAttrs = 1;
        cudaLaunchKernelEx(&cfg, level_out_kernel,
            l & 1, l,
            (const float*)(weights + (size_t)l * W_SZ * K_SZ),
            (const float*)(biases  + (size_t)l * W_SZ),
            (const int*)(parents + (size_t)l * W_SZ * K_SZ),
            (const unsigned char*)inv,
            out);
    }
}

// round 13
// speedup vs baseline: 3.6595x; 1.0494x over previous
#include <cuda_runtime.h>
#include <cuda_fp16.h>
#include <cstdint>

// Problem constants
#define B_SZ 256
#define W_SZ 4096
#define L_SZ 16
#define K_SZ 8

// Ping-pong activation scratch, fp16, transposed layout: h_t[n][b] (b fast).
// 2 * 4096 * 256 * 2B = 4 MB  -> fully L2-resident.
__device__ __half g_h[2][(size_t)W_SZ * B_SZ];

// Detected element width of inv_mask input: 1 (bool/uint8) or 4 (int32/float32).
__device__ int g_inv_width;

// ---------------------------------------------------------------------------
// Kernel 1: fused prior + transpose (+ PARALLEL inv width detection, block 0).
//   h_t[n][b] = (half) relu(obs[b][n] * pw[n] + pb[n])
// ---------------------------------------------------------------------------
__global__ void __launch_bounds__(256) prior_transpose_kernel(
    const float* __restrict__ obs,
    const float* __restrict__ pw,
    const float* __restrict__ pb,
    const unsigned char* __restrict__ inv)
{
    if (blockIdx.x == 0 && blockIdx.y == 0) {
        const int t = threadIdx.y * 32 + threadIdx.x;          // 0..255
        const int pred = (inv[t * 4 + 1] != 0) ? 1 : 0;        // coalesced
        const int any = __syncthreads_or(pred);
        if (t == 0) g_inv_width = any ? 1 : 4;
    }

    __shared__ float tile[32][33];
    const int n0 = blockIdx.x * 32;
    const int b0 = blockIdx.y * 32;
    const int tx = threadIdx.x;   // 0..31
    const int ty = threadIdx.y;   // 0..7

#pragma unroll
    for (int j = 0; j < 4; j++) {
        int b = b0 + ty + j * 8;
        tile[ty + j * 8][tx] = obs[(size_t)b * W_SZ + n0 + tx];  // tile[b_local][n_local]
    }
    __syncthreads();
#pragma unroll
    for (int j = 0; j < 4; j++) {
        int n = n0 + ty + j * 8;
        int b = b0 + tx;
        float v = tile[tx][ty + j * 8];
        v = fmaxf(fmaf(v, __ldg(pw + n), __ldg(pb + n)), 0.0f);
        g_h[0][(size_t)n * B_SZ + b] = __float2half_rn(v);
    }
#if __CUDA_ARCH__ >= 900
    cudaTriggerProgrammaticLaunchCompletion();
#endif
}

// ---------------------------------------------------------------------------
// Shared level math: PDL prologue loads params + gather addresses; post-sync
// all 8 LDG.128 gathers issue back-to-back (MLP=8), then convert+FMA.
// Returns the 8 fp32 relu outputs for (n, b..b+7) in acc[].
// ---------------------------------------------------------------------------
__device__ __forceinline__ void level_math(
    int src, int lvl, int n, int b,
    const float*         __restrict__ weights,
    const float*         __restrict__ biases,
    const int*           __restrict__ parents,
    const unsigned char* __restrict__ inv_base,
    float acc[8])
{
    // ---- PDL prologue: input-only loads + address math ----
    const int4*   pp = reinterpret_cast<const int4*>(parents + (size_t)n * K_SZ);
    const float4* wp = reinterpret_cast<const float4*>(weights + (size_t)n * K_SZ);
    int4   p0 = __ldg(pp);
    int4   p1 = __ldg(pp + 1);
    float4 w0 = __ldg(wp);
    float4 w1 = __ldg(wp + 1);
    float  bb = __ldg(biases + n);
    float  sw = ((w0.x + w0.y) + (w0.z + w0.w)) + ((w1.x + w1.y) + (w1.z + w1.w));
    float  base_inv = bb + sw;

    const __half* hb = g_h[src] + b;
    const int4* a0 = reinterpret_cast<const int4*>(hb + (((size_t)p0.x) << 8));
    const int4* a1 = reinterpret_cast<const int4*>(hb + (((size_t)p0.y) << 8));
    const int4* a2 = reinterpret_cast<const int4*>(hb + (((size_t)p0.z) << 8));
    const int4* a3 = reinterpret_cast<const int4*>(hb + (((size_t)p0.w) << 8));
    const int4* a4 = reinterpret_cast<const int4*>(hb + (((size_t)p1.x) << 8));
    const int4* a5 = reinterpret_cast<const int4*>(hb + (((size_t)p1.y) << 8));
    const int4* a6 = reinterpret_cast<const int4*>(hb + (((size_t)p1.z) << 8));
    const int4* a7 = reinterpret_cast<const int4*>(hb + (((size_t)p1.w) << 8));

#if __CUDA_ARCH__ >= 900
    cudaGridDependencySynchronize();   // previous level's stores now visible
#endif

    // ---- all 8 gathers in flight before any consumption (MLP = 8) ----
    int4 r0 = __ldg(a0);
    int4 r1 = __ldg(a1);
    int4 r2 = __ldg(a2);
    int4 r3 = __ldg(a3);
    int4 r4 = __ldg(a4);
    int4 r5 = __ldg(a5);
    int4 r6 = __ldg(a6);
    int4 r7 = __ldg(a7);

#pragma unroll
    for (int i = 0; i < 8; i++) acc[i] = 0.0f;

#define ACCUM(RAW, WV)                                                         \
    {                                                                          \
        float2 f0 = __half22float2(*reinterpret_cast<__half2*>(&(RAW).x));     \
        float2 f1 = __half22float2(*reinterpret_cast<__half2*>(&(RAW).y));     \
        float2 f2 = __half22float2(*reinterpret_cast<__half2*>(&(RAW).z));     \
        float2 f3 = __half22float2(*reinterpret_cast<__half2*>(&(RAW).w));     \
        acc[0] = fmaf((WV), f0.x, acc[0]); acc[1] = fmaf((WV), f0.y, acc[1]);  \
        acc[2] = fmaf((WV), f1.x, acc[2]); acc[3] = fmaf((WV), f1.y, acc[3]);  \
        acc[4] = fmaf((WV), f2.x, acc[4]); acc[5] = fmaf((WV), f2.y, acc[5]);  \
        acc[6] = fmaf((WV), f3.x, acc[6]); acc[7] = fmaf((WV), f3.y, acc[7]);  \
    }
    ACCUM(r0, w0.x)
    ACCUM(r1, w0.y)
    ACCUM(r2, w0.z)
    ACCUM(r3, w0.w)
    ACCUM(r4, w1.x)
    ACCUM(r5, w1.y)
    ACCUM(r6, w1.z)
    ACCUM(r7, w1.w)
#undef ACCUM

    // inv resolution (post-sync; hides under the gathers above).
    bool iv;
    if (g_inv_width == 4) {
        const unsigned* iw = reinterpret_cast<const unsigned*>(inv_base);
        iv = (__ldg(iw + (size_t)lvl * W_SZ + n) != 0u);
    } else {
        iv = (__ldg(inv_base + (size_t)lvl * W_SZ + n) != 0);
    }
    //  Σ w*(1-x) + b == (b + Σw) - Σ w*x
    float basev = iv ? base_inv : bb;
    float sgn   = iv ? -1.0f : 1.0f;

#pragma unroll
    for (int i = 0; i < 8; i++) acc[i] = fmaxf(fmaf(sgn, acc[i], basev), 0.0f);
}

// ---------------------------------------------------------------------------
// Kernel 2a: intermediate scan level (0..13) — stores fp16 to ping-pong.
// 128-thread CTAs (4 warps) x 1024 blocks: 1024/148 = 6.92 CTAs/SM ->
// near-perfect wave balance (vs 3.46 with 256-thread CTAs).
// ---------------------------------------------------------------------------
__global__ void __launch_bounds__(128, 8) level_kernel(
    int src,
    int lvl,
    const float*         __restrict__ weights,
    const float*         __restrict__ biases,
    const int*           __restrict__ parents,
    const unsigned char* __restrict__ inv_base)
{
    const int gid = blockIdx.x * 128 + threadIdx.x;
    const int n   = gid >> 5;          // 32 threads per n
    const int b   = (gid & 31) << 3;   // lane's 8-wide batch slice

    float acc[8];
    level_math(src, lvl, n, b, weights, biases, parents, inv_base, acc);

    __half2 o0 = __floats2half2_rn(acc[0], acc[1]);
    __half2 o1 = __floats2half2_rn(acc[2], acc[3]);
    __half2 o2 = __floats2half2_rn(acc[4], acc[5]);
    __half2 o3 = __floats2half2_rn(acc[6], acc[7]);
    int4 outv;
    outv.x = *reinterpret_cast<int*>(&o0);
    outv.y = *reinterpret_cast<int*>(&o1);
    outv.z = *reinterpret_cast<int*>(&o2);
    outv.w = *reinterpret_cast<int*>(&o3);
    *reinterpret_cast<int4*>(g_h[src ^ 1] + (size_t)n * B_SZ + b) = outv;

#if __CUDA_ARCH__ >= 900
    cudaTriggerProgrammaticLaunchCompletion();
#endif
}

// ---------------------------------------------------------------------------
// Kernel 2b: FINAL level (14) — fused output transpose.
// CTA covers 8 consecutive n. fp32 results staged in a bank-conflict-free
// smem tile (pitch 260: bank = (4n + b) % 32), then written to out[b][n]
// as fully-utilized 32B sectors. Skips the fp16 round-trip entirely.
// ---------------------------------------------------------------------------
#define TILE_PITCH 260
__global__ void __launch_bounds__(256, 4) level_out_kernel(
    int src,
    int lvl,
    const float*         __restrict__ weights,
    const float*         __restrict__ biases,
    const int*           __restrict__ parents,
    const unsigned char* __restrict__ inv_base,
    float* __restrict__ out)
{
    __shared__ float tile[8 * TILE_PITCH];

    const int lane = threadIdx.x & 31;
    const int w    = threadIdx.x >> 5;         // warp id in CTA = local n
    const int n0   = blockIdx.x * 8;
    const int n    = n0 + w;
    const int b    = lane << 3;

    float acc[8];
    level_math(src, lvl, n, b, weights, biases, parents, inv_base, acc);

    // Stage: tile[w][b..b+7] = acc.
    float* tp = tile + w * TILE_PITCH + b;
    *reinterpret_cast<float4*>(tp)     = make_float4(acc[0], acc[1], acc[2], acc[3]);
    *reinterpret_cast<float4*>(tp + 4) = make_float4(acc[4], acc[5], acc[6], acc[7]);
    __syncthreads();

    // Write: warp w owns b-range [w*32, w*32+32). Each iteration, 32 lanes
    // cover 4 b's x 8 n's -> 4 fully-utilized 32B sectors in out.
    const int nn = lane & 7;          // 0..7  (n offset)
    const int bq = lane >> 3;         // 0..3  (b offset within group)
#pragma unroll
    for (int j = 0; j < 8; j++) {
        int bb = w * 32 + j * 4 + bq;
        float v = tile[nn * TILE_PITCH + bb];
        out[(size_t)bb * W_SZ + n0 + nn] = v;
    }
}

// ---------------------------------------------------------------------------
// Launch: prior -> 14 intermediate levels -> fused final level, PDL-chained.
// ---------------------------------------------------------------------------
extern "C" void kernel_launch(void* const* d_in, const int* in_sizes, int n_in,
                              void* d_out, int out_size)
{
    const float*         obs     = (const float*)d_in[0];         // [B, W]
    const float*         pw      = (const float*)d_in[1];         // [W]
    const float*         pb      = (const float*)d_in[2];         // [W]
    const float*         weights = (const float*)d_in[3];         // [L-1, W, K]
    const float*         biases  = (const float*)d_in[4];         // [L-1, W]
    const int*           parents = (const int*)d_in[5];           // [L-1, W, K]
    const unsigned char* inv     = (const unsigned char*)d_in[6]; // [L-1, W]
    float*               out     = (float*)d_out;                 // [B, W]

    (void)in_sizes; (void)n_in; (void)out_size;

    // Prior + transpose into g_h[0] (also detects inv_mask element width)
    prior_transpose_kernel<<<dim3(W_SZ / 32, B_SZ / 32), dim3(32, 8)>>>(obs, pw, pb, inv);

    cudaLaunchAttribute attrs[1];
    attrs[0].id = cudaLaunchAttributeProgrammaticStreamSerialization;
    attrs[0].val.programmaticStreamSerializationAllowed = 1;

    // Levels 0..13: ping-pong g_h[0] <-> g_h[1], PDL-chained, 128-thr CTAs.
    const int blocks = (W_SZ * 32) / 128;  // 1024
    for (int l = 0; l < L_SZ - 2; l++) {
        cudaLaunchConfig_t cfg = {};
        cfg.gridDim  = dim3(blocks, 1, 1);
        cfg.blockDim = dim3(128, 1, 1);
        cfg.dynamicSmemBytes = 0;
        cfg.stream = 0;
        cfg.attrs = attrs;
        cfg.numAttrs = 1;
        cudaLaunchKernelEx(&cfg, level_kernel,
            l & 1, l,
            (const float*)(weights + (size_t)l * W_SZ * K_SZ),
            (const float*)(biases  + (size_t)l * W_SZ),
            (const int*)(parents + (size_t)l * W_SZ * K_SZ),
            (const unsigned char*)inv);
    }

    // Level 14: fused final level + output transpose (fp32, direct to out).
    {
        const int l = L_SZ - 2;  // 14
        cudaLaunchConfig_t cfg = {};
        cfg.gridDim  = dim3(W_SZ / 8, 1, 1);   // 512 CTAs x 8 warps
        cfg.blockDim = dim3(256, 1, 1);
        cfg.dynamicSmemBytes = 0;
        cfg.stream = 0;
        cfg.attrs = attrs;
        cfg.numAttrs = 1;
        cudaLaunchKernelEx(&cfg, level_out_kernel,
            l & 1, l,
            (const float*)(weights + (size_t)l * W_SZ * K_SZ),
            (const float*)(biases  + (size_t)l * W_SZ),
            (const int*)(parents + (size_t)l * W_SZ * K_SZ),
            (const unsigned char*)inv,
            out);
    }
}